// round 8
// baseline (speedup 1.0000x reference)
#include <cuda_runtime.h>
#include <math.h>

#define SIZE 64
#define NB 512
#define ST 256   // super-tile: j's per barrier period

// Scratch (device globals: allocation-free rule)
__device__ float g_pS[NB];             // per-block sum-exp partials
__device__ float g_pagg[NB * SIZE];    // per-block agg partials
__device__ unsigned g_done = 0;        // last-block counter (last block resets)

// Single fused kernel:
//   prologue: v = W^T a[64:]  (per block, W is L2-hot)
//   loop over 256-j super-tiles: energies (column reads) -> exp -> agg (row reads)
//   last block: reduce partials, out = sigmoid(W @ agg / S), reset counter.
__global__ __launch_bounds__(256) void k_main(const float* __restrict__ nx,
                                              const float* __restrict__ W,
                                              const float* __restrict__ a,
                                              float* __restrict__ out,
                                              int N, int nst) {
    __shared__ float vs[SIZE];
    __shared__ float4 smA[4][64];       // phase-A partials [ig][jq]
    __shared__ float pe[ST];            // p_j for current super-tile
    __shared__ float4 sm4[16 * 16];     // acc partials (epilogue)
    __shared__ float sred[256];
    __shared__ float sagg[4][SIZE];
    __shared__ float aggs[SIZE];
    __shared__ unsigned isLast;

    int t = threadIdx.x;

    // ---- Prologue: v[i] = sum_o a[64+o] * W[o*64+i] ----
    if (t < SIZE) {
        float v = 0.f;
#pragma unroll 16
        for (int o = 0; o < SIZE; o++)
            v = fmaf(__ldg(&a[SIZE + o]), __ldg(&W[o * SIZE + t]), v);
        vs[t] = v;
    }
    __syncthreads();

    const float4* nx4 = (const float4*)nx;
    int NQ = N >> 2;
    int jq = t & 63, ig = t >> 6;       // phase A
    int kq = t & 15, jl = t >> 4;       // phase B

    float4 acc = make_float4(0.f, 0.f, 0.f, 0.f);
    float sp = 0.f;

    for (int T = blockIdx.x; T < nst; T += gridDim.x) {
        int j0 = T * ST;
        // ---- Phase A: e_j = sum_i v[i]*flat[i*N+j], j in [j0, j0+256) ----
        float4 pa = make_float4(0.f, 0.f, 0.f, 0.f);
        int col = (j0 >> 2) + jq;
        if (col < NQ) {
#pragma unroll
            for (int u = 0; u < 16; u++) {
                int i = ig * 16 + u;
                float4 f = nx4[(size_t)i * NQ + col];
                float vi = vs[i];
                pa.x = fmaf(vi, f.x, pa.x);
                pa.y = fmaf(vi, f.y, pa.y);
                pa.z = fmaf(vi, f.z, pa.z);
                pa.w = fmaf(vi, f.w, pa.w);
            }
        }
        smA[ig][jq] = pa;
        __syncthreads();
        // ---- exp: thread t owns j = j0 + t ----
        {
            const float* s = (const float*)smA;   // float idx: ig*256 + jj
            float e = s[t] + s[256 + t] + s[512 + t] + s[768 + t];
            float p = (j0 + t < N) ? __expf(e) : 0.f;   // no max-shift: |e| small
            pe[t] = p;
            sp += p;
        }
        __syncthreads();
        // ---- Phase B: acc[k] += p_j * flat[j*64+k], rows contiguous ----
#pragma unroll
        for (int u = 0; u < 16; u++) {
            int jj = jl + 16 * u;
            int j = j0 + jj;
            if (j < N) {
                float4 f = nx4[(size_t)j * 16 + kq];
                float p = pe[jj];
                acc.x = fmaf(p, f.x, acc.x);
                acc.y = fmaf(p, f.y, acc.y);
                acc.z = fmaf(p, f.z, acc.z);
                acc.w = fmaf(p, f.w, acc.w);
            }
        }
        __syncthreads();   // pe must not be rewritten while phase B reads it
    }

    // ---- Block partials ----
    sm4[jl * 16 + kq] = acc;
    sred[t] = sp;
    __syncthreads();
    if (t < SIZE) {
        const float* s = (const float*)sm4;     // float idx: jl*64 + k
        float r = 0.f;
#pragma unroll
        for (int l = 0; l < 16; l++) r += s[l * 64 + t];
        g_pagg[blockIdx.x * SIZE + t] = r;
    }
#pragma unroll
    for (int off = 128; off > 0; off >>= 1) {
        if (t < off) sred[t] += sred[t + off];
        __syncthreads();
    }
    if (t == 0) g_pS[blockIdx.x] = sred[0];
    __threadfence();
    __syncthreads();
    if (t == 0) isLast = (atomicAdd(&g_done, 1u) == gridDim.x - 1u);
    __syncthreads();
    if (!isLast) return;

    // ---- Last block: final reduce + output (partials are L2-hot) ----
    float s = 0.f;
    for (int b = t; b < NB; b += 256) s += g_pS[b];
    __syncthreads();
    sred[t] = s;
    __syncthreads();
#pragma unroll
    for (int off = 128; off > 0; off >>= 1) {
        if (t < off) sred[t] += sred[t + off];
        __syncthreads();
    }

    int k = t & 63;
    int g = t >> 6;  // 0..3
    float av = 0.f;
#pragma unroll 8
    for (int b = g; b < NB; b += 4) av += g_pagg[b * SIZE + k];
    sagg[g][k] = av;
    __syncthreads();

    if (t < SIZE) {
        float S = sred[0];
        aggs[t] = (sagg[0][t] + sagg[1][t] + sagg[2][t] + sagg[3][t]) / S;
    }
    __syncthreads();

    if (t < SIZE) {
        float o = 0.f;
#pragma unroll 16
        for (int kk = 0; kk < SIZE; kk++)
            o = fmaf(W[t * SIZE + kk], aggs[kk], o);
        out[t] = 1.f / (1.f + __expf(-o));
    }
    if (t == 0) g_done = 0u;   // reset for next graph replay
}

extern "C" void kernel_launch(void* const* d_in, const int* in_sizes, int n_in,
                              void* d_out, int out_size) {
    // metadata order: x (64), n_x (N*64), W (64*64), a (128)
    const float* nx = (const float*)d_in[1];
    const float* W  = (const float*)d_in[2];
    const float* a  = (const float*)d_in[3];
    float* out = (float*)d_out;

    int N = in_sizes[1] / SIZE;        // 500000
    int nst = (N + ST - 1) / ST;       // 1954

    k_main<<<NB, 256>>>(nx, W, a, out, N, nst);
}